// round 1
// baseline (speedup 1.0000x reference)
#include <cuda_runtime.h>

#define BATCH 4
#define NN 2048
#define DIN 128
#define NH 4
#define HD 32
#define NEG 0.2f

#define BI 64
#define BJ 64

// scratch (no allocations allowed)
__device__ float g_h[(size_t)BATCH * NN * NH * HD];   // [b][n][head][d]
__device__ float g_ei[(size_t)BATCH * NN * NH];
__device__ float g_ej[(size_t)BATCH * NN * NH];

// ---------------------------------------------------------------------------
// Kernel A: h = x @ W^T  (per 16-row tile), fused ei/ej reductions
// block: 128 threads, handles (b, 16 rows of n)
// ---------------------------------------------------------------------------
__global__ __launch_bounds__(128) void proj_kernel(const float* __restrict__ x,
                                                   const float* __restrict__ W,
                                                   const float* __restrict__ a) {
    __shared__ float xs[16][DIN];      // 8 KB
    __shared__ float Ws[DIN][33];      // 32-wide k chunk, pad to 33 (conflict-free)

    const int t = threadIdx.x;
    const int blk = blockIdx.x;
    const int b = blk / (NN / 16);
    const int n0 = (blk % (NN / 16)) * 16;

    // stage x tile (coalesced float4)
    {
        const float4* xg = (const float4*)(x + ((size_t)b * NN + n0) * DIN);
        float4* xs4 = (float4*)&xs[0][0];
#pragma unroll
        for (int i = t; i < 16 * DIN / 4; i += 128) xs4[i] = xg[i];
    }

    float acc[16];
#pragma unroll
    for (int r = 0; r < 16; r++) acc[r] = 0.f;

    for (int kc = 0; kc < DIN; kc += 32) {
        __syncthreads();
        // stage W chunk: W[c][kc..kc+31]
#pragma unroll
        for (int idx = t; idx < DIN * 32; idx += 128) {
            int c = idx >> 5, kk = idx & 31;
            Ws[c][kk] = W[c * DIN + kc + kk];
        }
        __syncthreads();
#pragma unroll
        for (int kk = 0; kk < 32; kk++) {
            float wv = Ws[t][kk];            // banks (t+kk)%32 : conflict-free
#pragma unroll
            for (int r = 0; r < 16; r++)
                acc[r] = fmaf(xs[r][kc + kk], wv, acc[r]);  // broadcast
        }
    }

    // epilogue: write h, compute ei/ej per (b,n,head) via warp reduce
    const int head = t >> 5;
    const int d = t & 31;
    const float av1 = a[head * 2 * HD + d];        // a1[head][d]
    const float av2 = a[head * 2 * HD + HD + d];   // a2[head][d]

#pragma unroll
    for (int r = 0; r < 16; r++) {
        size_t n = (size_t)n0 + r;
        g_h[(((size_t)b * NN + n) * NH + head) * HD + d] = acc[r];
        float s1 = acc[r] * av1;
        float s2 = acc[r] * av2;
#pragma unroll
        for (int o = 16; o > 0; o >>= 1) {
            s1 += __shfl_xor_sync(0xffffffffu, s1, o);
            s2 += __shfl_xor_sync(0xffffffffu, s2, o);
        }
        if (d == 0) {
            g_ei[((size_t)b * NN + n) * NH + head] = s1;
            g_ej[((size_t)b * NN + n) * NH + head] = s2;
        }
    }
}

// ---------------------------------------------------------------------------
// Kernel B: masked softmax attention + attn@h, online-softmax, tiled GEMM.
// grid: B*H*(N/BI) = 512 CTAs, 128 threads.
// CTA handles (b, head, 64-row i block); loops over 64-wide j tiles.
// Thread GEMM micro-tile: 4 i x 4 d. (t&7)->d group, (t>>3)->i group.
// ---------------------------------------------------------------------------
__global__ __launch_bounds__(128) void attn_kernel(const int* __restrict__ adj,
                                                   float* __restrict__ out) {
    __shared__ float Hs[BJ][HD];          // 8 KB
    __shared__ float Ps[BI][BJ + 2];      // stride 66: conflict-free, float2-aligned
    __shared__ float ejs[BJ];
    __shared__ float eis[BI];
    __shared__ float msm[BI], lsm[BI], scalesm[BI];

    const int t = threadIdx.x;
    const int bx = blockIdx.x;
    const int ib = bx & 31;               // N/BI = 32
    const int head = (bx >> 5) & 3;
    const int b = bx >> 7;
    const int i0 = ib * BI;

    const int dgrp = t & 7;
    const int d0 = dgrp * 4;
    const int il0 = (t >> 3) * 4;         // local i base (16 groups * 4 = 64)

    const int warp = t >> 5;
    const int lane = t & 31;

    if (t < BI) {
        eis[t] = g_ei[((size_t)b * NN + i0 + t) * NH + head];
        msm[t] = -1e30f;
        lsm[t] = 0.f;
    }

    float4 acc[4];
#pragma unroll
    for (int ii = 0; ii < 4; ii++) acc[ii] = make_float4(0.f, 0.f, 0.f, 0.f);

    for (int j0 = 0; j0 < NN; j0 += BJ) {
        __syncthreads();   // previous GEMM done (and init visible on first pass)

        // stage Hs: 64 rows x 32 d  (512 float4, coalesced 128B per row)
#pragma unroll
        for (int idx = t; idx < BJ * HD / 4; idx += 128) {
            int jj = idx >> 3, f = idx & 7;
            ((float4*)&Hs[jj][0])[f] =
                *(const float4*)&g_h[(((size_t)b * NN + j0 + jj) * NH + head) * HD + f * 4];
        }
        if (t < BJ) ejs[t] = g_ej[((size_t)b * NN + j0 + t) * NH + head];
        __syncthreads();

        // ---- P-build: warp w handles rows [w*16, w*16+16) ----
        for (int rr = 0; rr < 16; rr++) {
            int i = warp * 16 + rr;
            int gi = i0 + i;
            int2 av = *(const int2*)(adj + (size_t)gi * NN + j0 + lane * 2);
            float eiv = eis[i];
            float e0 = eiv + ejs[lane * 2];
            float e1 = eiv + ejs[lane * 2 + 1];
            e0 = fmaxf(e0, NEG * e0);           // LeakyReLU
            e1 = fmaxf(e1, NEG * e1);
            bool v0 = (av.x != 0);
            bool v1 = (av.y != 0);
            float m0 = v0 ? e0 : -1e30f;
            float m1 = v1 ? e1 : -1e30f;
            float lm = fmaxf(m0, m1);
#pragma unroll
            for (int o = 16; o > 0; o >>= 1)
                lm = fmaxf(lm, __shfl_xor_sync(0xffffffffu, lm, o));
            float m_old = msm[i];
            float m_new = fmaxf(m_old, lm);
            float p0 = v0 ? __expf(e0 - m_new) : 0.f;
            float p1 = v1 ? __expf(e1 - m_new) : 0.f;
            float ps = p0 + p1;
#pragma unroll
            for (int o = 16; o > 0; o >>= 1)
                ps += __shfl_xor_sync(0xffffffffu, ps, o);
            Ps[i][lane * 2] = p0;
            Ps[i][lane * 2 + 1] = p1;
            if (lane == 0) {
                float sc = __expf(m_old - m_new);   // 0 on first real tile, 1 if unchanged
                lsm[i] = lsm[i] * sc + ps;
                msm[i] = m_new;
                scalesm[i] = sc;
            }
        }
        __syncthreads();

        // ---- rescale + GEMM: acc[4i][4d] += P[i][jj] * Hs[jj][d] ----
        {
            float s0 = scalesm[il0 + 0];
            float s1 = scalesm[il0 + 1];
            float s2 = scalesm[il0 + 2];
            float s3 = scalesm[il0 + 3];
            acc[0].x *= s0; acc[0].y *= s0; acc[0].z *= s0; acc[0].w *= s0;
            acc[1].x *= s1; acc[1].y *= s1; acc[1].z *= s1; acc[1].w *= s1;
            acc[2].x *= s2; acc[2].y *= s2; acc[2].z *= s2; acc[2].w *= s2;
            acc[3].x *= s3; acc[3].y *= s3; acc[3].z *= s3; acc[3].w *= s3;
        }
#pragma unroll 8
        for (int jj = 0; jj < BJ; jj++) {
            float4 hv = *(const float4*)&Hs[jj][d0];
            float p0 = Ps[il0 + 0][jj];
            float p1 = Ps[il0 + 1][jj];
            float p2 = Ps[il0 + 2][jj];
            float p3 = Ps[il0 + 3][jj];
            acc[0].x = fmaf(p0, hv.x, acc[0].x);
            acc[0].y = fmaf(p0, hv.y, acc[0].y);
            acc[0].z = fmaf(p0, hv.z, acc[0].z);
            acc[0].w = fmaf(p0, hv.w, acc[0].w);
            acc[1].x = fmaf(p1, hv.x, acc[1].x);
            acc[1].y = fmaf(p1, hv.y, acc[1].y);
            acc[1].z = fmaf(p1, hv.z, acc[1].z);
            acc[1].w = fmaf(p1, hv.w, acc[1].w);
            acc[2].x = fmaf(p2, hv.x, acc[2].x);
            acc[2].y = fmaf(p2, hv.y, acc[2].y);
            acc[2].z = fmaf(p2, hv.z, acc[2].z);
            acc[2].w = fmaf(p2, hv.w, acc[2].w);
            acc[3].x = fmaf(p3, hv.x, acc[3].x);
            acc[3].y = fmaf(p3, hv.y, acc[3].y);
            acc[3].z = fmaf(p3, hv.z, acc[3].z);
            acc[3].w = fmaf(p3, hv.w, acc[3].w);
        }
    }

    // epilogue: divide by l, write out[b, i, head*HD + d]
#pragma unroll
    for (int ii = 0; ii < 4; ii++) {
        float rl = 1.f / lsm[il0 + ii];
        float4 v = acc[ii];
        v.x *= rl; v.y *= rl; v.z *= rl; v.w *= rl;
        *(float4*)&out[(((size_t)b * NN + i0 + il0 + ii) * (NH * HD)) + head * HD + d0] = v;
    }
}

// ---------------------------------------------------------------------------
extern "C" void kernel_launch(void* const* d_in, const int* in_sizes, int n_in,
                              void* d_out, int out_size) {
    const float* x   = (const float*)d_in[0];
    const int*   adj = (const int*)d_in[1];
    const float* W   = (const float*)d_in[2];
    const float* a   = (const float*)d_in[3];
    float* out = (float*)d_out;

    proj_kernel<<<BATCH * (NN / 16), 128>>>(x, W, a);
    attn_kernel<<<BATCH * NH * (NN / BI), 128>>>(adj, out);
}

// round 4
// speedup vs baseline: 1.0015x; 1.0015x over previous
#include <cuda_runtime.h>

#define BATCH 4
#define NN 2048
#define DIN 128
#define NH 4
#define HD 32
#define NEG 0.2f

#define BI 32
#define BJ 64
#define PSTRIDE (2 * BJ + 4)   // 132 floats, conflict-free + 16B-aligned rows (528B)

typedef unsigned long long u64;

// scratch (no allocations allowed)
__device__ float g_h[(size_t)BATCH * NN * NH * HD];   // [b][n][head][d]
__device__ float g_ei[(size_t)BATCH * NN * NH];
__device__ float g_ej[(size_t)BATCH * NN * NH];

__device__ __forceinline__ void ffma2(u64& d, u64 a, u64 b) {
    asm("fma.rn.f32x2 %0, %1, %2, %0;" : "+l"(d) : "l"(a), "l"(b));
}

// ---------------------------------------------------------------------------
// Kernel A: h = x @ W^T (16-row tiles), fused ei/ej warp reductions
// ---------------------------------------------------------------------------
__global__ __launch_bounds__(128) void proj_kernel(const float* __restrict__ x,
                                                   const float* __restrict__ W,
                                                   const float* __restrict__ a) {
    __shared__ float xs[16][DIN];
    __shared__ float Ws[DIN][33];

    const int t = threadIdx.x;
    const int blk = blockIdx.x;
    const int b = blk / (NN / 16);
    const int n0 = (blk % (NN / 16)) * 16;

    {
        const float4* xg = (const float4*)(x + ((size_t)b * NN + n0) * DIN);
        float4* xs4 = (float4*)&xs[0][0];
#pragma unroll
        for (int i = t; i < 16 * DIN / 4; i += 128) xs4[i] = xg[i];
    }

    float acc[16];
#pragma unroll
    for (int r = 0; r < 16; r++) acc[r] = 0.f;

    for (int kc = 0; kc < DIN; kc += 32) {
        __syncthreads();
#pragma unroll
        for (int idx = t; idx < DIN * 32; idx += 128) {
            int c = idx >> 5, kk = idx & 31;
            Ws[c][kk] = W[c * DIN + kc + kk];
        }
        __syncthreads();
#pragma unroll
        for (int kk = 0; kk < 32; kk++) {
            float wv = Ws[t][kk];
#pragma unroll
            for (int r = 0; r < 16; r++)
                acc[r] = fmaf(xs[r][kc + kk], wv, acc[r]);
        }
    }

    const int head = t >> 5;
    const int d = t & 31;
    const float av1 = a[head * 2 * HD + d];
    const float av2 = a[head * 2 * HD + HD + d];

#pragma unroll
    for (int r = 0; r < 16; r++) {
        size_t n = (size_t)n0 + r;
        g_h[(((size_t)b * NN + n) * NH + head) * HD + d] = acc[r];
        float s1 = acc[r] * av1;
        float s2 = acc[r] * av2;
#pragma unroll
        for (int o = 16; o > 0; o >>= 1) {
            s1 += __shfl_xor_sync(0xffffffffu, s1, o);
            s2 += __shfl_xor_sync(0xffffffffu, s2, o);
        }
        if (d == 0) {
            g_ei[((size_t)b * NN + n) * NH + head] = s1;
            g_ej[((size_t)b * NN + n) * NH + head] = s2;
        }
    }
}

// ---------------------------------------------------------------------------
// Kernel B: masked attention, NO running max (e bounded, exp safe in fp32).
// grid: B*H*(N/BI) = 1024 CTAs, 128 threads.
// P-build: warp w rows [8w,8w+8), lane -> j pair; row sums in registers.
// GEMM: thread (ig=t>>3, dg=t&7): 2 i-rows x 4 d via packed fma.rn.f32x2.
// P stored duplicated {p,p} so FFMA2 needs no packing in the hot loop.
// ---------------------------------------------------------------------------
__global__ __launch_bounds__(128) void attn_kernel(const int* __restrict__ adj,
                                                   float* __restrict__ out) {
    __shared__ float Hs[BJ][HD];          // 8 KB
    __shared__ float Ps[BI][PSTRIDE];     // 16.9 KB (duplicated pairs)
    __shared__ float ejs[BJ];
    __shared__ float eis[BI];
    __shared__ float lsm[BI];

    const int t = threadIdx.x;
    const int bx = blockIdx.x;
    const int ib = bx & 63;               // N/BI = 64
    const int head = (bx >> 6) & 3;
    const int b = bx >> 8;
    const int i0 = ib * BI;

    const int warp = t >> 5;
    const int lane = t & 31;
    const int ig = t >> 3;                // 0..15 -> 2 rows each
    const int dg = t & 7;                 // 0..7  -> 4 d each
    const int irow = 2 * ig;

    if (t < BI) eis[t] = g_ei[((size_t)b * NN + i0 + t) * NH + head];
    __syncthreads();

    // per-warp row ei values (constant across tiles)
    float ei_r[8];
#pragma unroll
    for (int rr = 0; rr < 8; rr++) ei_r[rr] = eis[warp * 8 + rr];

    float ps0[8], ps1[8];
#pragma unroll
    for (int rr = 0; rr < 8; rr++) { ps0[rr] = 0.f; ps1[rr] = 0.f; }

    u64 acc[2][2] = {{0ull, 0ull}, {0ull, 0ull}};   // [i][dpair] f32x2

    for (int j0 = 0; j0 < NN; j0 += BJ) {
        __syncthreads();   // prev GEMM done before overwriting Hs/Ps

        // stage Hs: 64 rows x 32 d (512 float4, coalesced)
#pragma unroll
        for (int idx = t; idx < BJ * HD / 4; idx += 128) {
            int jj = idx >> 3, f = idx & 7;
            ((float4*)&Hs[jj][0])[f] =
                *(const float4*)&g_h[(((size_t)b * NN + j0 + jj) * NH + head) * HD + f * 4];
        }
        if (t < BJ) ejs[t] = g_ej[((size_t)b * NN + j0 + t) * NH + head];
        __syncthreads();

        const float ej0 = ejs[2 * lane];
        const float ej1 = ejs[2 * lane + 1];
        const int* arow = adj + (size_t)(i0 + warp * 8) * NN + j0 + lane * 2;

        // ---- P-build (no max, no shuffles) ----
#pragma unroll
        for (int rr = 0; rr < 8; rr++) {
            int2 av = *(const int2*)(arow + (size_t)rr * NN);
            float eiv = ei_r[rr];
            float e0 = eiv + ej0;
            float e1 = eiv + ej1;
            e0 = fmaxf(e0, NEG * e0);               // LeakyReLU
            e1 = fmaxf(e1, NEG * e1);
            float p0 = (av.x != 0) ? __expf(e0) : 0.f;
            float p1 = (av.y != 0) ? __expf(e1) : 0.f;
            ps0[rr] += p0;
            ps1[rr] += p1;
            *(float4*)&Ps[warp * 8 + rr][4 * lane] = make_float4(p0, p0, p1, p1);
        }
        __syncthreads();

        // ---- GEMM: acc[i][d] += P[i][jj] * Hs[jj][d], packed f32x2 ----
#pragma unroll 16
        for (int jj = 0; jj < BJ; jj++) {
            ulonglong2 hv = *(const ulonglong2*)&Hs[jj][4 * dg];   // 1 LDS128
            u64 pa = *(const u64*)&Ps[irow][2 * jj];               // {p,p}
            u64 pb = *(const u64*)&Ps[irow + 1][2 * jj];
            ffma2(acc[0][0], pa, hv.x);
            ffma2(acc[0][1], pa, hv.y);
            ffma2(acc[1][0], pb, hv.x);
            ffma2(acc[1][1], pb, hv.y);
        }
    }

    // ---- final row sums (once) ----
#pragma unroll
    for (int rr = 0; rr < 8; rr++) {
        float s = ps0[rr] + ps1[rr];
#pragma unroll
        for (int o = 16; o > 0; o >>= 1)
            s += __shfl_xor_sync(0xffffffffu, s, o);
        if (lane == 0) lsm[warp * 8 + rr] = s;
    }
    __syncthreads();

    // ---- epilogue: divide by row sum, store ----
#pragma unroll
    for (int ii = 0; ii < 2; ii++) {
        float rl = 1.f / lsm[irow + ii];
        union { u64 u; float2 f; } c0, c1;
        c0.u = acc[ii][0];
        c1.u = acc[ii][1];
        float4 v = make_float4(c0.f.x * rl, c0.f.y * rl, c1.f.x * rl, c1.f.y * rl);
        *(float4*)&out[((size_t)b * NN + i0 + irow + ii) * (NH * HD) + head * HD + 4 * dg] = v;
    }
}

// ---------------------------------------------------------------------------
extern "C" void kernel_launch(void* const* d_in, const int* in_sizes, int n_in,
                              void* d_out, int out_size) {
    const float* x   = (const float*)d_in[0];
    const int*   adj = (const int*)d_in[1];
    const float* W   = (const float*)d_in[2];
    const float* a   = (const float*)d_in[3];
    float* out = (float*)d_out;

    proj_kernel<<<BATCH * (NN / 16), 128>>>(x, W, a);
    attn_kernel<<<BATCH * NH * (NN / BI), 128>>>(adj, out);
}

// round 6
// speedup vs baseline: 1.4234x; 1.4213x over previous
#include <cuda_runtime.h>

#define BATCH 4
#define NN 2048
#define DIN 128
#define NH 4
#define HD 32
#define NEG 0.2f

#define BI 64
#define BJ 64
#define JPT 32            // j-pairs per tile
#define PSTR 66           // Pt row stride in u64 (even for 16B align, pad vs stride-64 conflicts)

typedef unsigned long long u64;

// scratch (no allocations allowed)
__device__ u64   g_hp[(size_t)BATCH * NH * (NN / 2) * HD];  // [b][head][npair][d] : {h[2n][d],h[2n+1][d]}
__device__ float g_ei[(size_t)BATCH * NH * NN];             // [b][head][n]
__device__ float g_ej[(size_t)BATCH * NH * NN];

__device__ __forceinline__ void ffma2(u64& d, u64 a, u64 b) {
    asm("fma.rn.f32x2 %0, %1, %2, %0;" : "+l"(d) : "l"(a), "l"(b));
}
__device__ __forceinline__ u64 add2(u64 a, u64 b) {
    u64 r; asm("add.rn.f32x2 %0, %1, %2;" : "=l"(r) : "l"(a), "l"(b)); return r;
}
__device__ __forceinline__ u64 pack2(float a, float b) {
    u64 r; asm("mov.b64 %0, {%1, %2};" : "=l"(r) : "f"(a), "f"(b)); return r;
}
__device__ __forceinline__ void unpack2(u64 v, float& a, float& b) {
    asm("mov.b64 {%0, %1}, %2;" : "=f"(a), "=f"(b) : "l"(v));
}

// ---------------------------------------------------------------------------
// Kernel A: h = x @ W^T (16-row tiles), fused ei/ej; writes j-pair-packed g_hp
// ---------------------------------------------------------------------------
__global__ __launch_bounds__(128) void proj_kernel(const float* __restrict__ x,
                                                   const float* __restrict__ W,
                                                   const float* __restrict__ a) {
    __shared__ float xs[16][DIN];
    __shared__ float Ws[DIN][33];

    const int t = threadIdx.x;
    const int blk = blockIdx.x;
    const int b = blk / (NN / 16);
    const int n0 = (blk % (NN / 16)) * 16;

    {
        const float4* xg = (const float4*)(x + ((size_t)b * NN + n0) * DIN);
        float4* xs4 = (float4*)&xs[0][0];
#pragma unroll
        for (int i = t; i < 16 * DIN / 4; i += 128) xs4[i] = xg[i];
    }

    float acc[16];
#pragma unroll
    for (int r = 0; r < 16; r++) acc[r] = 0.f;

    for (int kc = 0; kc < DIN; kc += 32) {
        __syncthreads();
#pragma unroll
        for (int idx = t; idx < DIN * 32; idx += 128) {
            int c = idx >> 5, kk = idx & 31;
            Ws[c][kk] = W[c * DIN + kc + kk];
        }
        __syncthreads();
#pragma unroll
        for (int kk = 0; kk < 32; kk++) {
            float wv = Ws[t][kk];
#pragma unroll
            for (int r = 0; r < 16; r++)
                acc[r] = fmaf(xs[r][kc + kk], wv, acc[r]);
        }
    }

    const int head = t >> 5;
    const int d = t & 31;
    const float av1 = a[head * 2 * HD + d];
    const float av2 = a[head * 2 * HD + HD + d];

    // packed h writes: pair rows (2r, 2r+1)
    u64* hp = g_hp + ((size_t)(b * NH + head) * (NN / 2) + n0 / 2) * HD + d;
#pragma unroll
    for (int r = 0; r < 8; r++)
        hp[(size_t)r * HD] = pack2(acc[2 * r], acc[2 * r + 1]);

    float* eip = g_ei + (size_t)(b * NH + head) * NN + n0;
    float* ejp = g_ej + (size_t)(b * NH + head) * NN + n0;
#pragma unroll
    for (int r = 0; r < 16; r++) {
        float s1 = acc[r] * av1;
        float s2 = acc[r] * av2;
#pragma unroll
        for (int o = 16; o > 0; o >>= 1) {
            s1 += __shfl_xor_sync(0xffffffffu, s1, o);
            s2 += __shfl_xor_sync(0xffffffffu, s2, o);
        }
        if (d == 0) { eip[r] = s1; ejp[r] = s2; }
    }
}

// ---------------------------------------------------------------------------
// Kernel B: grid B*H*(N/64) = 512 CTAs, 128 threads.
// P-build: warp w -> rows [16w,16w+16), lane -> j-pair; row sums in regs.
// GEMM: thread (jg=t>>6, ig=(t>>3)&7, dg=t&7): 8i x 4d tile, j-pair packed
// FFMA2; swizzled Pt/Hp rows for conflict-free LDS128. 2-way j-split with
// one-time cross-group reduction through smem.
// ---------------------------------------------------------------------------
__global__ __launch_bounds__(128, 4) void attn_kernel(const int* __restrict__ adj,
                                                      float* __restrict__ out) {
    __shared__ u64 Hp[JPT][HD];        // 8 KB  (row: swizzled d-chunks)
    __shared__ u64 Pt[JPT][PSTR];      // 16.9 KB (row jp: swizzled i-chunks)
    __shared__ float ejs[BJ];
    __shared__ float eis[BI];
    __shared__ float lsm[BI];

    const int t = threadIdx.x;
    const int bx = blockIdx.x;
    const int ib = bx & 31;            // N/BI = 32
    const int head = (bx >> 5) & 3;
    const int b = bx >> 7;
    const int i0 = ib * BI;

    const int warp = t >> 5;
    const int lane = t & 31;
    const int dg = t & 7;
    const int ig = (t >> 3) & 7;
    const int jg = t >> 6;

    const size_t bh = (size_t)(b * NH + head);
    if (t < BI) eis[t] = g_ei[bh * NN + i0 + t];

    float ps[16];
#pragma unroll
    for (int r = 0; r < 16; r++) ps[r] = 0.f;

    u64 acc[8][4];
#pragma unroll
    for (int i = 0; i < 8; i++)
#pragma unroll
        for (int d = 0; d < 4; d++) acc[i][d] = 0ull;

    const u64* hpg = g_hp + bh * (NN / 2) * HD;   // tile jp0*HD is flat 8KB
    const float* ejg = g_ej + bh * NN;

    for (int j0 = 0; j0 < NN; j0 += BJ) {
        __syncthreads();   // prev GEMM reads done

        // ---- stage Hp with d-chunk swizzle: chunk m(=d>>1) -> slot (m>>1)|((m&1)<<3)
        {
            const ulonglong2* src = (const ulonglong2*)(hpg + (size_t)(j0 / 2) * HD);
#pragma unroll
            for (int k = 0; k < 4; k++) {
                int q = k * 128 + t;               // chunk id: 32 jp x 16 m
                int jp = q >> 4, m = q & 15;
                int slot = (m >> 1) | ((m & 1) << 3);
                *(ulonglong2*)&Hp[jp][slot * 2] = src[q];
            }
        }
        if (t < BJ) ejs[t] = ejg[j0 + t];
        __syncthreads();

        // ---- P-build: rows 16*warp .. +16, lane -> jpair ----
        {
            const float ej0 = ejs[2 * lane];
            const float ej1 = ejs[2 * lane + 1];
            const int* arow = adj + (size_t)(i0 + warp * 16) * NN + j0 + 2 * lane;
#pragma unroll
            for (int rr = 0; rr < 16; rr++) {
                int2 av = *(const int2*)(arow + (size_t)rr * NN);
                float eiv = eis[warp * 16 + rr];
                float e0 = eiv + ej0;
                float e1 = eiv + ej1;
                e0 = fmaxf(e0, NEG * e0);
                e1 = fmaxf(e1, NEG * e1);
                float p0 = (av.x != 0) ? __expf(e0) : 0.f;
                float p1 = (av.y != 0) ? __expf(e1) : 0.f;
                ps[rr] += p0 + p1;
                int i = warp * 16 + rr;
                int m = i >> 1;
                int slot = (m >> 2) | ((m & 3) << 3);
                Pt[lane][slot * 2 + (i & 1)] = pack2(p0, p1);
            }
        }
        __syncthreads();

        // ---- GEMM: 16 jp steps per j-group ----
#pragma unroll 4
        for (int s = 0; s < 16; s++) {
            int jp = jg * 16 + s;
            const u64* prow = &Pt[jp][0];
            ulonglong2 pc0 = *(const ulonglong2*)(prow + ig * 2);
            ulonglong2 pc1 = *(const ulonglong2*)(prow + ig * 2 + 16);
            ulonglong2 pc2 = *(const ulonglong2*)(prow + ig * 2 + 32);
            ulonglong2 pc3 = *(const ulonglong2*)(prow + ig * 2 + 48);
            ulonglong2 h0 = *(const ulonglong2*)&Hp[jp][dg * 2];        // d0, d0+1
            ulonglong2 h1 = *(const ulonglong2*)&Hp[jp][dg * 2 + 16];   // d0+2, d0+3

            ffma2(acc[0][0], pc0.x, h0.x); ffma2(acc[0][1], pc0.x, h0.y);
            ffma2(acc[0][2], pc0.x, h1.x); ffma2(acc[0][3], pc0.x, h1.y);
            ffma2(acc[1][0], pc0.y, h0.x); ffma2(acc[1][1], pc0.y, h0.y);
            ffma2(acc[1][2], pc0.y, h1.x); ffma2(acc[1][3], pc0.y, h1.y);
            ffma2(acc[2][0], pc1.x, h0.x); ffma2(acc[2][1], pc1.x, h0.y);
            ffma2(acc[2][2], pc1.x, h1.x); ffma2(acc[2][3], pc1.x, h1.y);
            ffma2(acc[3][0], pc1.y, h0.x); ffma2(acc[3][1], pc1.y, h0.y);
            ffma2(acc[3][2], pc1.y, h1.x); ffma2(acc[3][3], pc1.y, h1.y);
            ffma2(acc[4][0], pc2.x, h0.x); ffma2(acc[4][1], pc2.x, h0.y);
            ffma2(acc[4][2], pc2.x, h1.x); ffma2(acc[4][3], pc2.x, h1.y);
            ffma2(acc[5][0], pc2.y, h0.x); ffma2(acc[5][1], pc2.y, h0.y);
            ffma2(acc[5][2], pc2.y, h1.x); ffma2(acc[5][3], pc2.y, h1.y);
            ffma2(acc[6][0], pc3.x, h0.x); ffma2(acc[6][1], pc3.x, h0.y);
            ffma2(acc[6][2], pc3.x, h1.x); ffma2(acc[6][3], pc3.x, h1.y);
            ffma2(acc[7][0], pc3.y, h0.x); ffma2(acc[7][1], pc3.y, h0.y);
            ffma2(acc[7][2], pc3.y, h1.x); ffma2(acc[7][3], pc3.y, h1.y);
        }
    }

    __syncthreads();   // all GEMM reads of Pt done; Pt reusable as reduction buffer

    // ---- final row sums (once) ----
#pragma unroll
    for (int rr = 0; rr < 16; rr++) {
        float s = ps[rr];
#pragma unroll
        for (int o = 16; o > 0; o >>= 1)
            s += __shfl_xor_sync(0xffffffffu, s, o);
        if (lane == 0) lsm[warp * 16 + rr] = s;
    }

    // ---- cross j-group reduction: group 1 stashes accs, group 0 adds ----
    u64* red = &Pt[0][0];
    if (jg == 1) {
        u64* dst = red + (size_t)(t & 63) * 32;
#pragma unroll
        for (int i = 0; i < 8; i++)
#pragma unroll
            for (int d = 0; d < 4; d++) dst[i * 4 + d] = acc[i][d];
    }
    __syncthreads();

    if (jg == 0) {
        const u64* srcr = red + (size_t)t * 32;
#pragma unroll
        for (int i = 0; i < 8; i++) {
            int gi = ig * 8 + i;
            float rl = 1.f / lsm[gi];
            float4 v;
            float lo, hi;
            u64 a0 = add2(acc[i][0], srcr[i * 4 + 0]);
            u64 a1 = add2(acc[i][1], srcr[i * 4 + 1]);
            u64 a2 = add2(acc[i][2], srcr[i * 4 + 2]);
            u64 a3 = add2(acc[i][3], srcr[i * 4 + 3]);
            unpack2(a0, lo, hi); v.x = (lo + hi) * rl;
            unpack2(a1, lo, hi); v.y = (lo + hi) * rl;
            unpack2(a2, lo, hi); v.z = (lo + hi) * rl;
            unpack2(a3, lo, hi); v.w = (lo + hi) * rl;
            *(float4*)&out[((size_t)b * NN + i0 + gi) * (NH * HD) + head * HD + dg * 4] = v;
        }
    }
}

// ---------------------------------------------------------------------------
extern "C" void kernel_launch(void* const* d_in, const int* in_sizes, int n_in,
                              void* d_out, int out_size) {
    const float* x   = (const float*)d_in[0];
    const int*   adj = (const int*)d_in[1];
    const float* W   = (const float*)d_in[2];
    const float* a   = (const float*)d_in[3];
    float* out = (float*)d_out;

    proj_kernel<<<BATCH * (NN / 16), 128>>>(x, W, a);
    attn_kernel<<<BATCH * NH * (NN / BI), 128>>>(adj, out);
}

// round 9
// speedup vs baseline: 3.8188x; 2.6828x over previous
#include <cuda_runtime.h>
#include <cuda_fp16.h>

#define BATCH 4
#define NN 2048
#define DIN 128
#define NH 4
#define HD 32
#define NEG 0.2f
#define L2E 1.4426950408889634f

typedef unsigned int u32;
typedef unsigned long long u64;

// scratch (no allocations allowed)
__device__ __half g_hh[(size_t)BATCH * NH * NN * HD];   // [b][head][n][d] fp16
__device__ float  g_ei[(size_t)BATCH * NH * NN];        // ei * log2(e)
__device__ float  g_ej[(size_t)BATCH * NH * NN];        // ej * log2(e)
__device__ u64    g_bits[(size_t)NN * (NN / 64)];       // [i][jtile] adjacency bitmask

// ---------------------------------------------------------------------------
// ldmatrix / mma helpers
// ---------------------------------------------------------------------------
__device__ __forceinline__ void ldsm4(u32& r0, u32& r1, u32& r2, u32& r3, u32 addr) {
    asm volatile("ldmatrix.sync.aligned.m8n8.x4.shared.b16 {%0,%1,%2,%3}, [%4];"
                 : "=r"(r0), "=r"(r1), "=r"(r2), "=r"(r3) : "r"(addr));
}
__device__ __forceinline__ void ldsm4t(u32& r0, u32& r1, u32& r2, u32& r3, u32 addr) {
    asm volatile("ldmatrix.sync.aligned.m8n8.x4.trans.shared.b16 {%0,%1,%2,%3}, [%4];"
                 : "=r"(r0), "=r"(r1), "=r"(r2), "=r"(r3) : "r"(addr));
}
__device__ __forceinline__ void mma16816(float* d, const u32* a, u32 b0, u32 b1) {
    asm volatile("mma.sync.aligned.m16n8k16.row.col.f32.f16.f16.f32 "
                 "{%0,%1,%2,%3}, {%4,%5,%6,%7}, {%8,%9}, {%0,%1,%2,%3};"
                 : "+f"(d[0]), "+f"(d[1]), "+f"(d[2]), "+f"(d[3])
                 : "r"(a[0]), "r"(a[1]), "r"(a[2]), "r"(a[3]), "r"(b0), "r"(b1));
}

// ---------------------------------------------------------------------------
// Kernel 0: pack adjacency into bitmask. warp -> (row, 64-wide jtile)
// ---------------------------------------------------------------------------
__global__ __launch_bounds__(256) void bits_kernel(const int* __restrict__ adj) {
    int gw = (blockIdx.x * 256 + threadIdx.x) >> 5;
    int lane = threadIdx.x & 31;
    int row = gw >> 5;
    int jt = gw & 31;
    const int* p = adj + (size_t)row * NN + jt * 64;
    u32 lo = __ballot_sync(0xffffffffu, p[lane] != 0);
    u32 hi = __ballot_sync(0xffffffffu, p[lane + 32] != 0);
    if (lane == 0) g_bits[(size_t)row * 32 + jt] = (u64)lo | ((u64)hi << 32);
}

// ---------------------------------------------------------------------------
// Kernel A: h = x @ W^T (16-row tiles); writes fp16 h + log2e-scaled ei/ej
// ---------------------------------------------------------------------------
__global__ __launch_bounds__(128) void proj_kernel(const float* __restrict__ x,
                                                   const float* __restrict__ W,
                                                   const float* __restrict__ a) {
    __shared__ float xs[16][DIN];
    __shared__ float Ws[DIN][33];

    const int t = threadIdx.x;
    const int blk = blockIdx.x;
    const int b = blk / (NN / 16);
    const int n0 = (blk % (NN / 16)) * 16;

    {
        const float4* xg = (const float4*)(x + ((size_t)b * NN + n0) * DIN);
        float4* xs4 = (float4*)&xs[0][0];
#pragma unroll
        for (int i = t; i < 16 * DIN / 4; i += 128) xs4[i] = xg[i];
    }

    float acc[16];
#pragma unroll
    for (int r = 0; r < 16; r++) acc[r] = 0.f;

    for (int kc = 0; kc < DIN; kc += 32) {
        __syncthreads();
#pragma unroll
        for (int idx = t; idx < DIN * 32; idx += 128) {
            int c = idx >> 5, kk = idx & 31;
            Ws[c][kk] = W[c * DIN + kc + kk];
        }
        __syncthreads();
#pragma unroll
        for (int kk = 0; kk < 32; kk++) {
            float wv = Ws[t][kk];
#pragma unroll
            for (int r = 0; r < 16; r++)
                acc[r] = fmaf(xs[r][kc + kk], wv, acc[r]);
        }
    }

    const int head = t >> 5;
    const int d = t & 31;
    const float av1 = a[head * 2 * HD + d];
    const float av2 = a[head * 2 * HD + HD + d];
    const size_t bh = (size_t)(b * NH + head);

    __half* hp = g_hh + (bh * NN + n0) * HD + d;
#pragma unroll
    for (int r = 0; r < 16; r++)
        hp[(size_t)r * HD] = __float2half(acc[r]);

    float* eip = g_ei + bh * NN + n0;
    float* ejp = g_ej + bh * NN + n0;
#pragma unroll
    for (int r = 0; r < 16; r++) {
        float s1 = acc[r] * av1;
        float s2 = acc[r] * av2;
#pragma unroll
        for (int o = 16; o > 0; o >>= 1) {
            s1 += __shfl_xor_sync(0xffffffffu, s1, o);
            s2 += __shfl_xor_sync(0xffffffffu, s2, o);
        }
        if (d == 0) { eip[r] = s1 * L2E; ejp[r] = s2 * L2E; }
    }
}

// ---------------------------------------------------------------------------
// Kernel B: attention via fp16 HMMA. grid B*H*(N/64) = 512 CTAs, 128 thr.
// Warp w owns i-rows [16w,16w+16): builds its fp16 P tile (ex2.f16x2, bitmask
// masked), then mma.m16n8k16: A=P (ldmatrix.x4), B=H (ldmatrix.x4.trans).
// 5th accumulator with ones-column B fragment yields the softmax row sums.
// ---------------------------------------------------------------------------
__global__ __launch_bounds__(128) void attn_kernel(float* __restrict__ out) {
    __shared__ __half Hs[64 * 40];    // row stride 40 halves (80B) : ldmatrix-safe
    __shared__ __half Ps[64 * 72];    // row stride 72 halves (144B): ldmatrix-safe
    __shared__ float ejs[64];
    __shared__ float eis_s[64];

    const int t = threadIdx.x;
    const int warp = t >> 5;
    const int lane = t & 31;
    const int bx = blockIdx.x;
    const int ib = bx & 31;
    const int head = (bx >> 5) & 3;
    const int b = bx >> 7;
    const int i0 = ib * 64;
    const size_t bh = (size_t)(b * NH + head);

    if (t < 64) eis_s[t] = g_ei[bh * NN + i0 + t];
    __syncthreads();

    float eil[16];
#pragma unroll
    for (int rr = 0; rr < 16; rr++) eil[rr] = eis_s[warp * 16 + rr];

    float acc[5][4];
#pragma unroll
    for (int n = 0; n < 5; n++)
#pragma unroll
        for (int q = 0; q < 4; q++) acc[n][q] = 0.f;

    const u32 bones = (lane < 4) ? 0x3C003C00u : 0u;   // fp16 1.0 pairs, col 0 only

    const u32 ps_smem = (u32)__cvta_generic_to_shared(Ps);
    const u32 hs_smem = (u32)__cvta_generic_to_shared(Hs);
    // ldmatrix per-lane base addresses
    const u32 aBase = ps_smem + (u32)(((warp * 16 + (lane & 15)) * 72 + (lane >> 4) * 8) * 2);
    const u32 bBase = hs_smem + (u32)(((lane & 15) * 40 + (lane >> 4) * 8) * 2);

    const u64* bitrow = g_bits + (size_t)(i0 + warp * 16) * 32;
    const __half* hsrc = g_hh + bh * NN * HD;
    const float* ejg = g_ej + bh * NN;
    __half* psrow = &Ps[(warp * 16) * 72 + 2 * lane];

    for (int jt = 0; jt < 32; jt++) {
        __syncthreads();   // previous GEMM reads of Hs done

        // stage H tile (64 rows x 32 d fp16), padded stride 40
        {
            const uint4* src = (const uint4*)(hsrc + (size_t)jt * 64 * HD);
#pragma unroll
            for (int k = 0; k < 2; k++) {
                int q = k * 128 + t;
                int row = q >> 2, c = q & 3;
                *(uint4*)&Hs[row * 40 + c * 8] = src[q];
            }
        }
        if (t < 64) ejs[t] = ejg[jt * 64 + t];
        __syncthreads();

        const float ejl0 = ejs[2 * lane];
        const float ejl1 = ejs[2 * lane + 1];
        const u32 sh = (2 * lane) & 31;

        // ---- P build (warp-local, log2 domain, fp16) ----
#pragma unroll
        for (int rr = 0; rr < 16; rr++) {
            u64 bits = bitrow[rr * 32 + jt];            // uniform broadcast load
            u32 sel = (lane < 16) ? (u32)bits : (u32)(bits >> 32);
            bool m0 = (sel >> sh) & 1;
            bool m1 = (sel >> (sh + 1)) & 1;
            float e0 = eil[rr] + ejl0;
            float e1 = eil[rr] + ejl1;
            e0 = fmaxf(e0, NEG * e0);                   // LeakyReLU (log2-scaled: scale>0 commutes)
            e1 = fmaxf(e1, NEG * e1);
            e0 = m0 ? e0 : -100.f;                      // 2^-100 -> fp16 0
            e1 = m1 ? e1 : -100.f;
            __half2 eh = __floats2half2_rn(e0, e1);
            u32 ph;
            asm("ex2.approx.f16x2 %0, %1;" : "=r"(ph) : "r"(*(u32*)&eh));
            *(u32*)(psrow + rr * 72) = ph;
        }
        __syncwarp();

        // ---- HMMA: D[16 x 32] += P[16 x 64] * H[64 x 32]  (+ ones column) ----
#pragma unroll
        for (int kc = 0; kc < 4; kc++) {
            u32 a[4];
            ldsm4(a[0], a[1], a[2], a[3], aBase + kc * 32);
            u32 b0[4], b1[4];
            ldsm4t(b0[0], b0[1], b0[2], b0[3], bBase + (u32)((kc * 16 * 40) * 2));
            ldsm4t(b1[0], b1[1], b1[2], b1[3], bBase + (u32)((kc * 16 * 40 + 16) * 2));
            mma16816(acc[0], a, b0[0], b0[1]);
            mma16816(acc[1], a, b0[2], b0[3]);
            mma16816(acc[2], a, b1[0], b1[1]);
            mma16816(acc[3], a, b1[2], b1[3]);
            mma16816(acc[4], a, bones, bones);
        }
    }

    // ---- epilogue: row sums live in acc[4] col 0 (lanes with lane%4==0) ----
    float s0 = __shfl_sync(0xffffffffu, acc[4][0], lane & ~3);   // row lane>>2
    float s1 = __shfl_sync(0xffffffffu, acc[4][2], lane & ~3);   // row lane>>2 + 8
    float inv0 = 1.f / s0;
    float inv1 = 1.f / s1;

    const int r0 = lane >> 2;
    const int c0 = 2 * (lane & 3);
    const size_t orow0 = ((size_t)b * NN + i0 + warp * 16 + r0) * (NH * HD) + head * HD;
    const size_t orow1 = orow0 + (size_t)8 * (NH * HD);
#pragma unroll
    for (int nc = 0; nc < 4; nc++) {
        *(float2*)&out[orow0 + nc * 8 + c0] = make_float2(acc[nc][0] * inv0, acc[nc][1] * inv0);
        *(float2*)&out[orow1 + nc * 8 + c0] = make_float2(acc[nc][2] * inv1, acc[nc][3] * inv1);
    }
}

// ---------------------------------------------------------------------------
extern "C" void kernel_launch(void* const* d_in, const int* in_sizes, int n_in,
                              void* d_out, int out_size) {
    const float* x   = (const float*)d_in[0];
    const int*   adj = (const int*)d_in[1];
    const float* W   = (const float*)d_in[2];
    const float* a   = (const float*)d_in[3];
    float* out = (float*)d_out;

    bits_kernel<<<NN * 32 / 8, 256>>>(adj);
    proj_kernel<<<BATCH * (NN / 16), 128>>>(x, W, a);
    attn_kernel<<<BATCH * NH * (NN / 64), 128>>>(out);
}

// round 10
// speedup vs baseline: 5.3054x; 1.3893x over previous
#include <cuda_runtime.h>
#include <cuda_fp16.h>

#define BATCH 4
#define NN 2048
#define DIN 128
#define NH 4
#define HD 32
#define NEG 0.2f
#define L2E 1.4426950408889634f

typedef unsigned int u32;
typedef unsigned long long u64;

// scratch (no allocations allowed)
__device__ __half g_hh[(size_t)BATCH * NH * NN * HD];   // [b][head][n][d] fp16
__device__ float  g_ei[(size_t)BATCH * NH * NN];        // ei * log2(e)
__device__ float  g_ej[(size_t)BATCH * NH * NN];        // ej * log2(e)
__device__ u64    g_bits[(size_t)NN * (NN / 64)];       // [i][jtile] adjacency bitmask

// ---------------------------------------------------------------------------
// helpers
// ---------------------------------------------------------------------------
__device__ __forceinline__ void ldsm4t(u32& r0, u32& r1, u32& r2, u32& r3, u32 addr) {
    asm volatile("ldmatrix.sync.aligned.m8n8.x4.trans.shared.b16 {%0,%1,%2,%3}, [%4];"
                 : "=r"(r0), "=r"(r1), "=r"(r2), "=r"(r3) : "r"(addr));
}
__device__ __forceinline__ void mma16816(float* d, const u32* a, u32 b0, u32 b1) {
    asm volatile("mma.sync.aligned.m16n8k16.row.col.f32.f16.f16.f32 "
                 "{%0,%1,%2,%3}, {%4,%5,%6,%7}, {%8,%9}, {%0,%1,%2,%3};"
                 : "+f"(d[0]), "+f"(d[1]), "+f"(d[2]), "+f"(d[3])
                 : "r"(a[0]), "r"(a[1]), "r"(a[2]), "r"(a[3]), "r"(b0), "r"(b1));
}
__device__ __forceinline__ void cp16(u32 dst, const void* src) {
    asm volatile("cp.async.cg.shared.global [%0], [%1], 16;" :: "r"(dst), "l"(src));
}
// P fragment pair: e = ei + ej (log2 domain), leaky, 2^e, mask by adjacency bits 0,1
__device__ __forceinline__ u32 pfrag(__half2 ei2, __half2 ej2, u32 bits, __half2 neg2) {
    __half2 e = __hadd2(ei2, ej2);
    e = __hmax2(e, __hmul2(e, neg2));
    u32 p;
    asm("ex2.approx.f16x2 %0, %1;" : "=r"(p) : "r"(*(u32*)&e));
    u32 m = ((u32)(-(int)(bits & 1u)) & 0x0000FFFFu) |
            ((u32)(-(int)(bits & 2u)) & 0xFFFF0000u);
    return p & m;
}

// ---------------------------------------------------------------------------
// Kernel 0: adjacency -> bitmask, byte-granular writer (no ballots).
// thread -> 8 adjacency ints (2 x int4) -> 1 byte. 512K threads.
// ---------------------------------------------------------------------------
__global__ __launch_bounds__(256) void bits_kernel(const int* __restrict__ adj) {
    int tid = blockIdx.x * 256 + threadIdx.x;       // 0 .. 512K-1
    int row = tid >> 8;                             // 256 bytes per row
    int b8 = tid & 255;
    const int4* p = (const int4*)(adj + (size_t)row * NN + b8 * 8);
    int4 v0 = p[0];
    int4 v1 = p[1];
    u32 byte = (u32)(v0.x != 0) | ((u32)(v0.y != 0) << 1) |
               ((u32)(v0.z != 0) << 2) | ((u32)(v0.w != 0) << 3) |
               ((u32)(v1.x != 0) << 4) | ((u32)(v1.y != 0) << 5) |
               ((u32)(v1.z != 0) << 6) | ((u32)(v1.w != 0) << 7);
    ((unsigned char*)g_bits)[(size_t)row * 256 + b8] = (unsigned char)byte;
}

// ---------------------------------------------------------------------------
// Kernel A: h = x @ W^T (16-row tiles); fp16 h + log2e-scaled ei/ej
// ---------------------------------------------------------------------------
__global__ __launch_bounds__(128) void proj_kernel(const float* __restrict__ x,
                                                   const float* __restrict__ W,
                                                   const float* __restrict__ a) {
    __shared__ float xs[16][DIN];
    __shared__ float Ws[DIN][33];

    const int t = threadIdx.x;
    const int blk = blockIdx.x;
    const int b = blk / (NN / 16);
    const int n0 = (blk % (NN / 16)) * 16;

    {
        const float4* xg = (const float4*)(x + ((size_t)b * NN + n0) * DIN);
        float4* xs4 = (float4*)&xs[0][0];
#pragma unroll
        for (int i = t; i < 16 * DIN / 4; i += 128) xs4[i] = xg[i];
    }

    float acc[16];
#pragma unroll
    for (int r = 0; r < 16; r++) acc[r] = 0.f;

    for (int kc = 0; kc < DIN; kc += 32) {
        __syncthreads();
#pragma unroll
        for (int idx = t; idx < DIN * 32; idx += 128) {
            int c = idx >> 5, kk = idx & 31;
            Ws[c][kk] = W[c * DIN + kc + kk];
        }
        __syncthreads();
#pragma unroll
        for (int kk = 0; kk < 32; kk++) {
            float wv = Ws[t][kk];
#pragma unroll
            for (int r = 0; r < 16; r++)
                acc[r] = fmaf(xs[r][kc + kk], wv, acc[r]);
        }
    }

    const int head = t >> 5;
    const int d = t & 31;
    const float av1 = a[head * 2 * HD + d];
    const float av2 = a[head * 2 * HD + HD + d];
    const size_t bh = (size_t)(b * NH + head);

    __half* hp = g_hh + (bh * NN + n0) * HD + d;
#pragma unroll
    for (int r = 0; r < 16; r++)
        hp[(size_t)r * HD] = __float2half(acc[r]);

    float* eip = g_ei + bh * NN + n0;
    float* ejp = g_ej + bh * NN + n0;
#pragma unroll
    for (int r = 0; r < 16; r++) {
        float s1 = acc[r] * av1;
        float s2 = acc[r] * av2;
#pragma unroll
        for (int o = 16; o > 0; o >>= 1) {
            s1 += __shfl_xor_sync(0xffffffffu, s1, o);
            s2 += __shfl_xor_sync(0xffffffffu, s2, o);
        }
        if (d == 0) { eip[r] = s1 * L2E; ejp[r] = s2 * L2E; }
    }
}

// ---------------------------------------------------------------------------
// Kernel B: attention. 512 CTAs x 128 thr (4 warps, 16 i-rows each).
// P built directly in mma A-fragment registers (half2 math + ex2.f16x2,
// bit-derived AND masks). H tiles double-buffered via cp.async; ej converted
// one tile ahead; bitmasks register-prefetched. One barrier per tile.
// 5th accumulator with ones-column B fragment = softmax row sums.
// ---------------------------------------------------------------------------
__global__ __launch_bounds__(128) void attn_kernel(float* __restrict__ out) {
    __shared__ __half Hs[2][64 * 40];     // 10.2 KB, row stride 40 halves
    __shared__ __half2 ejh2s[2][32];

    const int t = threadIdx.x;
    const int warp = t >> 5;
    const int lane = t & 31;
    const int g = lane >> 2;
    const int q = lane & 3;
    const int bx = blockIdx.x;
    const int ib = bx & 31;
    const int head = (bx >> 5) & 3;
    const int b = bx >> 7;
    const int i0 = ib * 64;
    const size_t bh = (size_t)(b * NH + head);

    const int r_lo = i0 + warp * 16 + g;
    const __half2 eil2 = __float2half2_rn(g_ei[bh * NN + r_lo]);
    const __half2 eih2 = __float2half2_rn(g_ei[bh * NN + r_lo + 8]);
    const __half2 neg2 = __float2half2_rn(NEG);

    const u64* bitlo = g_bits + (size_t)r_lo * 32;
    const u64* bithi = bitlo + 8 * 32;

    const __half* hsrc = g_hh + bh * NN * HD;
    const float* ejg = g_ej + bh * NN;

    const u32 hs0 = (u32)__cvta_generic_to_shared(&Hs[0][0]);
    const u32 hs1 = (u32)__cvta_generic_to_shared(&Hs[1][0]);

    float acc[5][4];
#pragma unroll
    for (int n = 0; n < 5; n++)
#pragma unroll
        for (int c = 0; c < 4; c++) acc[n][c] = 0.f;

    const u32 bones = (lane < 4) ? 0x3C003C00u : 0u;   // ones in col 0

    // ---- preamble: prefetch tile 0 into buffer 0 ----
    {
        const uint4* src = (const uint4*)hsrc;
#pragma unroll
        for (int k = 0; k < 2; k++) {
            int qq = k * 128 + t;
            int row = qq >> 2, c = qq & 3;
            cp16(hs0 + (u32)((row * 40 + c * 8) * 2), src + qq);
        }
        if (t < 32) {
            float2 v = *(const float2*)(ejg + 2 * t);
            ejh2s[0][t] = __floats2half2_rn(v.x, v.y);
        }
        asm volatile("cp.async.commit_group;" ::: "memory");
    }
    u64 ml = bitlo[0];
    u64 mh = bithi[0];

    for (int jt = 0; jt < 32; jt++) {
        const int buf = jt & 1;
        asm volatile("cp.async.wait_group 0;" ::: "memory");
        __syncthreads();   // buf visible to all; buf^1 free for overwrite

        // ---- prefetch next tile into buf^1 ----
        u64 ml_n = 0, mh_n = 0;
        if (jt + 1 < 32) {
            const uint4* src = (const uint4*)(hsrc + (size_t)(jt + 1) * 64 * HD);
            u32 hb = buf ? hs0 : hs1;
#pragma unroll
            for (int k = 0; k < 2; k++) {
                int qq = k * 128 + t;
                int row = qq >> 2, c = qq & 3;
                cp16(hb + (u32)((row * 40 + c * 8) * 2), src + qq);
            }
            if (t < 32) {
                float2 v = *(const float2*)(ejg + (jt + 1) * 64 + 2 * t);
                ejh2s[buf ^ 1][t] = __floats2half2_rn(v.x, v.y);
            }
            ml_n = bitlo[jt + 1];
            mh_n = bithi[jt + 1];
        }
        asm volatile("cp.async.commit_group;" ::: "memory");

        // ---- compute on buf ----
        const u32 bB = (buf ? hs1 : hs0) +
                       (u32)((((lane & 15) * 40) + (lane >> 4) * 8) * 2);
        const __half2* ejrow = ejh2s[buf];

        // per-lane mask windows: pre-shift by 2q, then 16-bit windows per kc
        const u64 mls = ml >> (2 * q);
        const u64 mhs = mh >> (2 * q);
        const u32 lo_l = (u32)mls, hi_l = (u32)(mls >> 32);
        const u32 lo_h = (u32)mhs, hi_h = (u32)(mhs >> 32);
        u32 wl[4], wh[4];
        wl[0] = lo_l; wl[1] = __funnelshift_r(lo_l, hi_l, 16); wl[2] = hi_l; wl[3] = hi_l >> 16;
        wh[0] = lo_h; wh[1] = __funnelshift_r(lo_h, hi_h, 16); wh[2] = hi_h; wh[3] = hi_h >> 16;

#pragma unroll
        for (int kc = 0; kc < 4; kc++) {
            __half2 ej0 = ejrow[kc * 8 + q];        // cols 2q, 2q+1
            __half2 ej1 = ejrow[kc * 8 + q + 4];    // cols 2q+8, 2q+9
            u32 a[4];
            a[0] = pfrag(eil2, ej0, wl[kc], neg2);
            a[1] = pfrag(eih2, ej0, wh[kc], neg2);
            a[2] = pfrag(eil2, ej1, wl[kc] >> 8, neg2);
            a[3] = pfrag(eih2, ej1, wh[kc] >> 8, neg2);

            u32 b0[4], b1[4];
            ldsm4t(b0[0], b0[1], b0[2], b0[3], bB + (u32)((kc * 16 * 40) * 2));
            ldsm4t(b1[0], b1[1], b1[2], b1[3], bB + (u32)((kc * 16 * 40 + 16) * 2));
            mma16816(acc[0], a, b0[0], b0[1]);
            mma16816(acc[1], a, b0[2], b0[3]);
            mma16816(acc[2], a, b1[0], b1[1]);
            mma16816(acc[3], a, b1[2], b1[3]);
            mma16816(acc[4], a, bones, bones);
        }

        ml = ml_n;
        mh = mh_n;
    }

    // ---- epilogue: row sums in acc[4] col 0 (lanes with lane%4==0) ----
    float s0 = __shfl_sync(0xffffffffu, acc[4][0], lane & ~3);
    float s1 = __shfl_sync(0xffffffffu, acc[4][2], lane & ~3);
    float inv0 = 1.f / s0;
    float inv1 = 1.f / s1;

    const int c0 = 2 * (lane & 3);
    const size_t orow0 = ((size_t)b * NN + i0 + warp * 16 + g) * (NH * HD) + head * HD;
    const size_t orow1 = orow0 + (size_t)8 * (NH * HD);
#pragma unroll
    for (int nc = 0; nc < 4; nc++) {
        *(float2*)&out[orow0 + nc * 8 + c0] = make_float2(acc[nc][0] * inv0, acc[nc][1] * inv0);
        *(float2*)&out[orow1 + nc * 8 + c0] = make_float2(acc[nc][2] * inv1, acc[nc][3] * inv1);
    }
}

// ---------------------------------------------------------------------------
extern "C" void kernel_launch(void* const* d_in, const int* in_sizes, int n_in,
                              void* d_out, int out_size) {
    const float* x   = (const float*)d_in[0];
    const int*   adj = (const int*)d_in[1];
    const float* W   = (const float*)d_in[2];
    const float* a   = (const float*)d_in[3];
    float* out = (float*)d_out;

    bits_kernel<<<NN * NN / 8 / 256, 256>>>(adj);
    proj_kernel<<<BATCH * (NN / 16), 128>>>(x, W, a);
    attn_kernel<<<BATCH * NH * (NN / 64), 128>>>(out);
}